// round 1
// baseline (speedup 1.0000x reference)
#include <cuda_runtime.h>

#define G     512
#define C     48
#define C4    12                 // C / 4
#define PLANE_F4 (G * G * C4)    // float4 elements per transposed plane
#define LINE_F4  (G * C4)        // float4 elements per transposed line
#define PPB   32                 // points per block in sampler

// Scratch (allowed: __device__ globals). 3 * 512*512*48 floats = 151 MB.
__device__ float4 g_planeT[3ULL * PLANE_F4];
__device__ float4 g_lineT[3ULL * LINE_F4];

// ---------------------------------------------------------------------------
// Transpose planes: in [C][G*G] (channel-major)  ->  g_planeT [G*G][C]
// Conflict-free 48x32 smem tile; coalesced LDG and STG.
// ---------------------------------------------------------------------------
__global__ void transpose_plane_kernel(const float* __restrict__ p0,
                                       const float* __restrict__ p1,
                                       const float* __restrict__ p2) {
    __shared__ float tile[C][33];
    const int pid = blockIdx.y;
    const float* in = (pid == 0) ? p0 : (pid == 1) ? p1 : p2;
    float* out = reinterpret_cast<float*>(g_planeT + (size_t)pid * PLANE_F4);

    const int j0   = blockIdx.x * 32;
    const int lane = threadIdx.x & 31;
    const int w    = threadIdx.x >> 5;   // 0..7

    #pragma unroll
    for (int c = w; c < C; c += 8)
        tile[c][lane] = in[(size_t)c * (G * G) + j0 + lane];
    __syncthreads();

    #pragma unroll
    for (int k = 0; k < 6; k++) {
        int l = threadIdx.x + k * 256;   // 0..1535
        int j = l / C;
        int c = l % C;
        out[(size_t)(j0 + j) * C + c] = tile[c][j];
    }
}

// ---------------------------------------------------------------------------
// Transpose lines: in [C][G] -> g_lineT [G][C]
// ---------------------------------------------------------------------------
__global__ void transpose_line_kernel(const float* __restrict__ l0,
                                      const float* __restrict__ l1,
                                      const float* __restrict__ l2) {
    __shared__ float tile[C][33];
    const int pid = blockIdx.y;
    const float* in = (pid == 0) ? l0 : (pid == 1) ? l1 : l2;
    float* out = reinterpret_cast<float*>(g_lineT + (size_t)pid * LINE_F4);

    const int j0   = blockIdx.x * 32;
    const int lane = threadIdx.x & 31;
    const int w    = threadIdx.x >> 5;

    #pragma unroll
    for (int c = w; c < C; c += 8)
        tile[c][lane] = in[c * G + j0 + lane];
    __syncthreads();

    #pragma unroll
    for (int k = 0; k < 6; k++) {
        int l = threadIdx.x + k * 256;
        int j = l / C;
        int c = l % C;
        out[(j0 + j) * C + c] = tile[c][j];
    }
}

// ---------------------------------------------------------------------------
// Sampler
// ---------------------------------------------------------------------------
__device__ __forceinline__ float4 lerp4(float4 a, float4 b, float w) {
    float4 r;
    r.x = fmaf(w, b.x - a.x, a.x);
    r.y = fmaf(w, b.y - a.y, a.y);
    r.z = fmaf(w, b.z - a.z, a.z);
    r.w = fmaf(w, b.w - a.w, a.w);
    return r;
}

__global__ __launch_bounds__(384)
void sample_kernel(const float* __restrict__ xyz,
                   float* __restrict__ out, int N) {
    __shared__ int   s_poff[3][PPB];
    __shared__ int   s_pdx[3][PPB];
    __shared__ int   s_pdy[3][PPB];
    __shared__ float s_wx[3][PPB];
    __shared__ float s_wy[3][PPB];
    __shared__ int   s_loff[3][PPB];
    __shared__ int   s_ldz[3][PPB];
    __shared__ float s_wz[3][PPB];
    __shared__ float s_feat[3 * C][PPB + 1];   // padded: conflict-free phase-2 reads

    const int n0  = blockIdx.x * PPB;
    const int tid = threadIdx.x;

    // ---- Phase 0: per-point indices & weights (32 threads) ----
    if (tid < PPB) {
        int n = n0 + tid;
        float x = 0.f, y = 0.f, z = 0.f;
        if (n < N) {
            x = xyz[3 * n + 0];
            y = xyz[3 * n + 1];
            z = xyz[3 * n + 2];
        }
        // MAT_MODE = [(0,1),(0,2),(1,2)]: gx maps to W (ix), gy to H (iy)
        // VEC_MODE = [2,1,0]
        const float gxs[3] = {x, x, y};
        const float gys[3] = {y, z, z};
        const float gzs[3] = {z, y, x};
        #pragma unroll
        for (int m = 0; m < 3; m++) {
            float ix   = (gxs[m] + 1.0f) * 0.5f * (float)(G - 1);
            float iy   = (gys[m] + 1.0f) * 0.5f * (float)(G - 1);
            float ix0f = fminf(fmaxf(floorf(ix), 0.0f), (float)(G - 1));
            float iy0f = fminf(fmaxf(floorf(iy), 0.0f), (float)(G - 1));
            int ix0 = (int)ix0f;
            int iy0 = (int)iy0f;
            s_poff[m][tid] = (iy0 * G + ix0) * C4;      // float4 units
            s_pdx[m][tid]  = (ix0 < G - 1) ? C4 : 0;
            s_pdy[m][tid]  = (iy0 < G - 1) ? G * C4 : 0;
            s_wx[m][tid]   = ix - ix0f;
            s_wy[m][tid]   = iy - iy0f;

            float iz   = (gzs[m] + 1.0f) * 0.5f * (float)(G - 1);
            float iz0f = fminf(fmaxf(floorf(iz), 0.0f), (float)(G - 1));
            int iz0 = (int)iz0f;
            s_loff[m][tid] = iz0 * C4;
            s_ldz[m][tid]  = (iz0 < G - 1) ? C4 : 0;
            s_wz[m][tid]   = iz - iz0f;
        }
    }
    __syncthreads();

    // ---- Phase 1: gather + interpolate. Thread = (channel-quad, point). ----
    {
        const int c4 = tid % C4;   // lanes 0..11 share a point -> contiguous 192B
        const int p  = tid / C4;   // 0..31
        #pragma unroll
        for (int m = 0; m < 3; m++) {
            const float4* __restrict__ P = g_planeT + (size_t)m * PLANE_F4;
            const float4* __restrict__ L = g_lineT + (size_t)m * LINE_F4;
            const int   off = s_poff[m][p] + c4;
            const int   dx  = s_pdx[m][p];
            const int   dy  = s_pdy[m][p];
            const float wx  = s_wx[m][p];
            const float wy  = s_wy[m][p];
            const int   lo  = s_loff[m][p] + c4;
            const int   dz  = s_ldz[m][p];
            const float wz  = s_wz[m][p];

            float4 v00 = __ldg(P + off);
            float4 v01 = __ldg(P + off + dx);
            float4 v10 = __ldg(P + off + dy);
            float4 v11 = __ldg(P + off + dy + dx);
            float4 l0  = __ldg(L + lo);
            float4 l1  = __ldg(L + lo + dz);

            float4 top = lerp4(v00, v01, wx);
            float4 bot = lerp4(v10, v11, wx);
            float4 pl  = lerp4(top, bot, wy);
            float4 ln  = lerp4(l0, l1, wz);

            const int c = c4 * 4;
            s_feat[m * C + c + 0][p] = pl.x * ln.x;
            s_feat[m * C + c + 1][p] = pl.y * ln.y;
            s_feat[m * C + c + 2][p] = pl.z * ln.z;
            s_feat[m * C + c + 3][p] = pl.w * ln.w;
        }
    }
    __syncthreads();

    // ---- Phase 2: coalesced store. Warp = one channel-quad, lanes = points. ----
    {
        const int cr = tid >> 5;   // 0..11
        const int p  = tid & 31;
        const int n  = n0 + p;
        if (n < N) {
            #pragma unroll
            for (int m = 0; m < 3; m++) {
                #pragma unroll
                for (int k = 0; k < 4; k++) {
                    const int c = cr * 4 + k;
                    out[(size_t)(m * C + c) * N + n] = s_feat[m * C + c][p];
                }
            }
        }
    }
}

// ---------------------------------------------------------------------------
extern "C" void kernel_launch(void* const* d_in, const int* in_sizes, int n_in,
                              void* d_out, int out_size) {
    const float* xyz = (const float*)d_in[0];
    const float* p0  = (const float*)d_in[1];
    const float* p1  = (const float*)d_in[2];
    const float* p2  = (const float*)d_in[3];
    const float* l0  = (const float*)d_in[4];
    const float* l1  = (const float*)d_in[5];
    const float* l2  = (const float*)d_in[6];
    const int N = in_sizes[0] / 3;

    dim3 tpg(G * G / 32, 3);
    transpose_plane_kernel<<<tpg, 256>>>(p0, p1, p2);
    dim3 tlg(G / 32, 3);
    transpose_line_kernel<<<tlg, 256>>>(l0, l1, l2);

    int nb = (N + PPB - 1) / PPB;
    sample_kernel<<<nb, 384>>>(xyz, (float*)d_out, N);
}

// round 4
// speedup vs baseline: 1.6795x; 1.6795x over previous
#include <cuda_runtime.h>
#include <cuda_fp16.h>

#define G     512
#define GG    (G * G)
#define C     48
#define C2    (C / 2)
#define PPB   64                  // points per block in sampler
#define GRP   6                   // channel groups of 8 per point
#define THREADS (PPB * GRP)       // 384

// fp16 scratch (75.5 MB planes + 147 KB lines), layout [texel][channel]
__device__ __half g_planeH[3ULL * GG * C];
__device__ __half g_lineH[3ULL * G * C];

// ---------------------------------------------------------------------------
// Transpose + fp32->fp16 convert: in [C][GG] -> g_planeH [GG][C]
// 64 texels per block; float2 smem reads, half2 coalesced stores.
// ---------------------------------------------------------------------------
__global__ void tpose_plane_kernel(const float* __restrict__ p0,
                                   const float* __restrict__ p1,
                                   const float* __restrict__ p2) {
    __shared__ float tile[64][50];   // [j][c], pad 50 keeps float2 reads aligned+conflict-free
    const int pid = blockIdx.y;
    const float* in = (pid == 0) ? p0 : (pid == 1) ? p1 : p2;
    __half* out = g_planeH + (size_t)pid * GG * C;
    const int j0 = blockIdx.x * 64;

    #pragma unroll
    for (int i = threadIdx.x; i < C * 64; i += 256) {
        int c = i >> 6;
        int j = i & 63;
        tile[j][c] = in[(size_t)c * GG + j0 + j];   // coalesced 256B runs
    }
    __syncthreads();

    __half2* o2 = reinterpret_cast<__half2*>(out) + (size_t)j0 * C2;
    #pragma unroll
    for (int i = threadIdx.x; i < 64 * C2; i += 256) {
        int j  = i / C2;
        int c2 = i % C2;
        float2 v = *reinterpret_cast<const float2*>(&tile[j][2 * c2]);
        o2[i] = __float22half2_rn(v);               // fully coalesced 1KB/warp... 4B/thread
    }
}

__global__ void tpose_line_kernel(const float* __restrict__ l0,
                                  const float* __restrict__ l1,
                                  const float* __restrict__ l2) {
    __shared__ float tile[64][50];
    const int pid = blockIdx.y;
    const float* in = (pid == 0) ? l0 : (pid == 1) ? l1 : l2;
    __half* out = g_lineH + (size_t)pid * G * C;
    const int j0 = blockIdx.x * 64;

    #pragma unroll
    for (int i = threadIdx.x; i < C * 64; i += 256) {
        int c = i >> 6;
        int j = i & 63;
        tile[j][c] = in[c * G + j0 + j];
    }
    __syncthreads();

    __half2* o2 = reinterpret_cast<__half2*>(out) + (size_t)j0 * C2;
    #pragma unroll
    for (int i = threadIdx.x; i < 64 * C2; i += 256) {
        int j  = i / C2;
        int c2 = i % C2;
        float2 v = *reinterpret_cast<const float2*>(&tile[j][2 * c2]);
        o2[i] = __float22half2_rn(v);
    }
}

// ---------------------------------------------------------------------------
// Sampler: thread = (channel-octet, point). 6 lanes x 16B per texel gather.
// ---------------------------------------------------------------------------
__global__ __launch_bounds__(THREADS)
void sample_kernel(const float* __restrict__ xyz,
                   float* __restrict__ out, int N) {
    __shared__ int   s_t[3][PPB];
    __shared__ int   s_dx[3][PPB];
    __shared__ int   s_dy[3][PPB];
    __shared__ float s_wx[3][PPB];
    __shared__ float s_wy[3][PPB];
    __shared__ int   s_lz[3][PPB];
    __shared__ int   s_dz[3][PPB];
    __shared__ float s_wz[3][PPB];
    __shared__ float s_feat[3 * C][PPB + 1];   // 144 x 65 fp32

    const int n0  = blockIdx.x * PPB;
    const int tid = threadIdx.x;

    // ---- Phase 0: per-point indices & weights (64 threads) ----
    if (tid < PPB) {
        int n = n0 + tid;
        float x = 0.f, y = 0.f, z = 0.f;
        if (n < N) {
            x = xyz[3 * n + 0];
            y = xyz[3 * n + 1];
            z = xyz[3 * n + 2];
        }
        // MAT_MODE = [(0,1),(0,2),(1,2)], VEC_MODE = [2,1,0]
        const float gxs[3] = {x, x, y};
        const float gys[3] = {y, z, z};
        const float gzs[3] = {z, y, x};
        #pragma unroll
        for (int m = 0; m < 3; m++) {
            float ix   = (gxs[m] + 1.0f) * 0.5f * (float)(G - 1);
            float iy   = (gys[m] + 1.0f) * 0.5f * (float)(G - 1);
            float ix0f = fminf(fmaxf(floorf(ix), 0.0f), (float)(G - 1));
            float iy0f = fminf(fmaxf(floorf(iy), 0.0f), (float)(G - 1));
            int ix0 = (int)ix0f;
            int iy0 = (int)iy0f;
            s_t[m][tid]  = iy0 * G + ix0;
            s_dx[m][tid] = (ix0 < G - 1) ? 1 : 0;
            s_dy[m][tid] = (iy0 < G - 1) ? G : 0;
            s_wx[m][tid] = ix - ix0f;
            s_wy[m][tid] = iy - iy0f;

            float iz   = (gzs[m] + 1.0f) * 0.5f * (float)(G - 1);
            float iz0f = fminf(fmaxf(floorf(iz), 0.0f), (float)(G - 1));
            int iz0 = (int)iz0f;
            s_lz[m][tid] = iz0;
            s_dz[m][tid] = (iz0 < G - 1) ? 1 : 0;
            s_wz[m][tid] = iz - iz0f;
        }
    }
    __syncthreads();

    // ---- Phase 1: gather fp16, interpolate fp32, stage to smem ----
    {
        const int c8 = tid % GRP;    // 0..5, lanes contiguous within a texel (96B)
        const int p  = tid / GRP;    // 0..63
        #pragma unroll
        for (int m = 0; m < 3; m++) {
            const __half* P = g_planeH + (size_t)m * GG * C;
            const __half* L = g_lineH + (size_t)m * G * C;
            const int   t  = s_t[m][p];
            const int   dx = s_dx[m][p];
            const int   dy = s_dy[m][p];
            const float wx = s_wx[m][p];
            const float wy = s_wy[m][p];
            const int   lz = s_lz[m][p];
            const int   dz = s_dz[m][p];
            const float wz = s_wz[m][p];

            uint4 q00 = __ldg(reinterpret_cast<const uint4*>(P + (size_t)t * C) + c8);
            uint4 q01 = __ldg(reinterpret_cast<const uint4*>(P + (size_t)(t + dx) * C) + c8);
            uint4 q10 = __ldg(reinterpret_cast<const uint4*>(P + (size_t)(t + dy) * C) + c8);
            uint4 q11 = __ldg(reinterpret_cast<const uint4*>(P + (size_t)(t + dy + dx) * C) + c8);
            uint4 ql0 = __ldg(reinterpret_cast<const uint4*>(L + (size_t)lz * C) + c8);
            uint4 ql1 = __ldg(reinterpret_cast<const uint4*>(L + (size_t)(lz + dz) * C) + c8);

            const unsigned* u00 = reinterpret_cast<const unsigned*>(&q00);
            const unsigned* u01 = reinterpret_cast<const unsigned*>(&q01);
            const unsigned* u10 = reinterpret_cast<const unsigned*>(&q10);
            const unsigned* u11 = reinterpret_cast<const unsigned*>(&q11);
            const unsigned* ul0 = reinterpret_cast<const unsigned*>(&ql0);
            const unsigned* ul1 = reinterpret_cast<const unsigned*>(&ql1);

            const int row = m * C + c8 * 8;
            #pragma unroll
            for (int q = 0; q < 4; q++) {
                float2 a = __half22float2(*reinterpret_cast<const __half2*>(&u00[q]));
                float2 b = __half22float2(*reinterpret_cast<const __half2*>(&u01[q]));
                float2 c = __half22float2(*reinterpret_cast<const __half2*>(&u10[q]));
                float2 d = __half22float2(*reinterpret_cast<const __half2*>(&u11[q]));
                float2 e = __half22float2(*reinterpret_cast<const __half2*>(&ul0[q]));
                float2 f = __half22float2(*reinterpret_cast<const __half2*>(&ul1[q]));

                float2 top, bot, pl, ln;
                top.x = fmaf(wx, b.x - a.x, a.x);
                top.y = fmaf(wx, b.y - a.y, a.y);
                bot.x = fmaf(wx, d.x - c.x, c.x);
                bot.y = fmaf(wx, d.y - c.y, c.y);
                pl.x  = fmaf(wy, bot.x - top.x, top.x);
                pl.y  = fmaf(wy, bot.y - top.y, top.y);
                ln.x  = fmaf(wz, f.x - e.x, e.x);
                ln.y  = fmaf(wz, f.y - e.y, e.y);

                s_feat[row + 2 * q + 0][p] = pl.x * ln.x;
                s_feat[row + 2 * q + 1][p] = pl.y * ln.y;
            }
        }
    }
    __syncthreads();

    // ---- Phase 2: coalesced fp32 stores; warp = 32 points of one row ----
    {
        const int p = tid & 63;      // point within block
        const int r0 = tid >> 6;     // 0..5
        const int n = n0 + p;
        if (n < N) {
            #pragma unroll
            for (int i = 0; i < 24; i++) {
                const int r = r0 + i * 6;      // 0..143
                out[(size_t)r * N + n] = s_feat[r][p];
            }
        }
    }
}

// ---------------------------------------------------------------------------
extern "C" void kernel_launch(void* const* d_in, const int* in_sizes, int n_in,
                              void* d_out, int out_size) {
    const float* xyz = (const float*)d_in[0];
    const float* p0  = (const float*)d_in[1];
    const float* p1  = (const float*)d_in[2];
    const float* p2  = (const float*)d_in[3];
    const float* l0  = (const float*)d_in[4];
    const float* l1  = (const float*)d_in[5];
    const float* l2  = (const float*)d_in[6];
    const int N = in_sizes[0] / 3;

    dim3 tpg(GG / 64, 3);
    tpose_plane_kernel<<<tpg, 256>>>(p0, p1, p2);
    dim3 tlg(G / 64, 3);
    tpose_line_kernel<<<tlg, 256>>>(l0, l1, l2);

    int nb = (N + PPB - 1) / PPB;
    sample_kernel<<<nb, THREADS>>>(xyz, (float*)d_out, N);
}